// round 5
// baseline (speedup 1.0000x reference)
#include <cuda_runtime.h>
#include <math.h>

// SpatialGRU 32x32 wavefront, B=64, U=64, C=64.
// R4: diagonal-parallel persistent kernel, 148 CTAs (1 per SM), per-cell flag
// sync, Z computed in place into the precomputed x@W+bias buffer.

#define TPB 256
#define G   148

__device__ float g_x[1024 * 4096];       // x[t][b][c]
__device__ float g_XZ[1024 * 28672];     // x@W+bias -> overwritten with Z[t]
__device__ float g_xWij[1024 * 4096];    // x@W_ij + b_ij
__device__ float g_S[1024 * 4096];       // h state per cell
__device__ int   g_zdone[1024];          // counts to 7
__device__ int   g_hdone[1024];          // counts to 2

// ---------------------------------------------------------------------------
__global__ void k_init() {
    int idx = blockIdx.x * blockDim.x + threadIdx.x;
    if (idx < 1024) { g_zdone[idx] = 0; g_hdone[idx] = 0; }
}

// ---------------------------------------------------------------------------
// transpose inputs (B,C,32,32) -> g_x[t][b][c]
__global__ void k_transpose(const float* __restrict__ in) {
    __shared__ float tile[32][33];
    int b = blockIdx.z;
    int t0 = blockIdx.x * 32;
    int c0 = blockIdx.y * 32;
    int tx = threadIdx.x, ty = threadIdx.y;
    tile[ty][tx] = in[b * 65536 + (c0 + ty) * 1024 + t0 + tx];
    __syncthreads();
    g_x[(t0 + ty) * 4096 + b * 64 + c0 + tx] = tile[tx][ty];
}

// ---------------------------------------------------------------------------
// Precompute: XZ[t] = x[t]@W[192:256,:] + bias[:448];  xWij[t] = x[t]@W_ij + b_ij
// grid (1024, 8), block 256. ct 0..6 -> 64-col slices of XZ; ct==7 -> xWij.
__global__ void k_pre(const float* __restrict__ W, const float* __restrict__ Wij,
                      const float* __restrict__ bias) {
    __shared__ float sXT[64 * 65];
    __shared__ float sB[64 * 64];
    int t = blockIdx.x, ct = blockIdx.y, tid = threadIdx.x;
    for (int idx = tid; idx < 4096; idx += TPB) {
        int rr = idx >> 6, k = idx & 63;
        sXT[k * 65 + rr] = g_x[t * 4096 + idx];
        sB[idx] = (ct < 7) ? W[(192 + rr) * 448 + ct * 64 + k] : Wij[rr * 64 + k];
    }
    __syncthreads();
    int r = tid & 63;
    int cb = (tid >> 6) << 4;
    const float* bsrc = (ct < 7) ? (bias + ct * 64 + cb) : (bias + 448 + cb);
    float acc[16];
#pragma unroll
    for (int s = 0; s < 16; ++s) acc[s] = bsrc[s];
#pragma unroll 4
    for (int k = 0; k < 64; ++k) {
        float a = sXT[k * 65 + r];
        const float4* bp = (const float4*)&sB[k * 64 + cb];
        float4 b0 = bp[0], b1 = bp[1], b2 = bp[2], b3 = bp[3];
        acc[0]  += a * b0.x; acc[1]  += a * b0.y; acc[2]  += a * b0.z; acc[3]  += a * b0.w;
        acc[4]  += a * b1.x; acc[5]  += a * b1.y; acc[6]  += a * b1.z; acc[7]  += a * b1.w;
        acc[8]  += a * b2.x; acc[9]  += a * b2.y; acc[10] += a * b2.z; acc[11] += a * b2.w;
        acc[12] += a * b3.x; acc[13] += a * b3.y; acc[14] += a * b3.z; acc[15] += a * b3.w;
    }
    float* o = (ct < 7) ? &g_XZ[t * 28672 + r * 448 + ct * 64 + cb]
                        : &g_xWij[t * 4096 + r * 64 + cb];
#pragma unroll
    for (int s = 0; s < 16; ++s) o[s] = acc[s];
}

// ---------------------------------------------------------------------------
// Persistent diagonal-parallel scan. grid 148, block 256, 1 CTA/SM.
// p1 unit: (cell, 64-col slice) -> Z slice in place into g_XZ, bump zdone.
// p2 unit: (cell, 32-col half)  -> G=r*hcat, @U_rec, gates, h, bump hdone.
extern "C" __global__ void __launch_bounds__(TPB, 1)
k_scan(const float* __restrict__ W, const float* __restrict__ Urec,
       float* __restrict__ out) {
    extern __shared__ float sm[];
    float* sB  = sm;             // p1: W slice [192][64] ; p2: U slice [192][32]
    float* sAT = sm + 12288;     // [192][65] hcat^T (p1) / G^T (p2)

    int g = blockIdx.x;
    int tid = threadIdx.x;
    int r = tid & 63;
    int cb = (tid >> 6) << 4;     // p1: 16-col group
    int n0 = (tid >> 6) << 3;     // p2: 8-col group

    for (int d = 0; d < 63; ++d) {
        int i0 = d > 31 ? d - 31 : 0;
        int i1 = d < 31 ? d : 31;
        int nc = i1 - i0 + 1;

        // ================= phase 1 =================
        int n1 = nc * 7;
        for (int u = g; u < n1; u += G) {
            int c = u % nc, s = u / nc;
            int i = i0 + c, j = d - i, t = i * 32 + j;

            if (tid == 0) {
                if (i > 0)          while (((volatile int*)g_hdone)[t - 32] < 2) {}
                if (j > 0)          while (((volatile int*)g_hdone)[t - 1]  < 2) {}
                if (i > 0 && j > 0) while (((volatile int*)g_hdone)[t - 33] < 2) {}
            }
            __syncthreads();

            const float* srcT = (i > 0)          ? &g_S[(t - 32) * 4096] : (const float*)0;
            const float* srcL = (j > 0)          ? &g_S[(t - 1)  * 4096] : (const float*)0;
            const float* srcD = (i > 0 && j > 0) ? &g_S[(t - 33) * 4096] : (const float*)0;

            for (int idx = tid; idx < 12288; idx += TPB) {
                int k = idx >> 6, n = idx & 63;
                sB[idx] = W[k * 448 + s * 64 + n];
            }
            for (int idx = tid; idx < 4096; idx += TPB) {
                int rr = idx >> 6, c2 = idx & 63;
                sAT[c2 * 65 + rr]         = srcT ? __ldcg(&srcT[idx]) : 0.f;
                sAT[(64 + c2) * 65 + rr]  = srcL ? __ldcg(&srcL[idx]) : 0.f;
                sAT[(128 + c2) * 65 + rr] = srcD ? __ldcg(&srcD[idx]) : 0.f;
            }
            __syncthreads();

            float* xz = &g_XZ[t * 28672 + r * 448 + s * 64 + cb];
            float acc[16];
#pragma unroll
            for (int q = 0; q < 16; ++q) acc[q] = __ldcg(&xz[q]);
#pragma unroll 4
            for (int k = 0; k < 192; ++k) {
                float a = sAT[k * 65 + r];
                const float4* bp = (const float4*)&sB[k * 64 + cb];
                float4 b0 = bp[0], b1 = bp[1], b2 = bp[2], b3 = bp[3];
                acc[0]  += a * b0.x; acc[1]  += a * b0.y; acc[2]  += a * b0.z; acc[3]  += a * b0.w;
                acc[4]  += a * b1.x; acc[5]  += a * b1.y; acc[6]  += a * b1.z; acc[7]  += a * b1.w;
                acc[8]  += a * b2.x; acc[9]  += a * b2.y; acc[10] += a * b2.z; acc[11] += a * b2.w;
                acc[12] += a * b3.x; acc[13] += a * b3.y; acc[14] += a * b3.z; acc[15] += a * b3.w;
            }
#pragma unroll
            for (int q = 0; q < 16; ++q) xz[q] = acc[q];
            __threadfence();
            __syncthreads();
            if (tid == 0) atomicAdd(&g_zdone[t], 1);
        }

        // ================= phase 2 =================
        int n2 = nc * 2;
        for (int u = g; u < n2; u += G) {
            int c = u % nc, half = u / nc;
            int i = i0 + c, j = d - i, t = i * 32 + j;

            if (tid == 0) while (((volatile int*)g_zdone)[t] < 7) {}
            __syncthreads();

            const float* srcT = (i > 0)          ? &g_S[(t - 32) * 4096] : (const float*)0;
            const float* srcL = (j > 0)          ? &g_S[(t - 1)  * 4096] : (const float*)0;
            const float* srcD = (i > 0 && j > 0) ? &g_S[(t - 33) * 4096] : (const float*)0;
            const float* Z = &g_XZ[t * 28672];

            // G^T[c2][rr] = sigmoid(Z[rr][c2]) * concat[hL|hT|hD][rr][c2&63]
            for (int idx = tid; idx < 12288; idx += TPB) {
                int rr = idx / 192;
                int c2 = idx - rr * 192;
                float z = __ldcg(&Z[rr * 448 + c2]);
                float sg = 1.f / (1.f + __expf(-z));
                const float* hs = (c2 < 64) ? srcL : ((c2 < 128) ? srcT : srcD);
                float hv = hs ? __ldcg(&hs[rr * 64 + (c2 & 63)]) : 0.f;
                sAT[c2 * 65 + rr] = sg * hv;
            }
            for (int idx = tid; idx < 6144; idx += TPB) {
                int k = idx >> 5, n = idx & 31;
                sB[idx] = Urec[k * 64 + half * 32 + n];
            }
            __syncthreads();

            float p[8];
#pragma unroll
            for (int q = 0; q < 8; ++q) p[q] = 0.f;
#pragma unroll 4
            for (int k = 0; k < 192; ++k) {
                float a = sAT[k * 65 + r];
                const float4* up = (const float4*)&sB[k * 32 + n0];
                float4 u0 = up[0], u1 = up[1];
                p[0] += a * u0.x; p[1] += a * u0.y; p[2] += a * u0.z; p[3] += a * u0.w;
                p[4] += a * u1.x; p[5] += a * u1.y; p[6] += a * u1.z; p[7] += a * u1.w;
            }

#pragma unroll
            for (int q = 0; q < 8; ++q) {
                int n = half * 32 + n0 + q;
                float zi = __ldcg(&Z[r * 448 + 192 + n]);
                float zl = __ldcg(&Z[r * 448 + 256 + n]);
                float zt = __ldcg(&Z[r * 448 + 320 + n]);
                float zd = __ldcg(&Z[r * 448 + 384 + n]);
                float m = fmaxf(fmaxf(zi, zl), fmaxf(zt, zd));
                float ei = __expf(zi - m), el = __expf(zl - m);
                float et = __expf(zt - m), ed = __expf(zd - m);
                float inv = 1.f / (ei + el + et + ed);
                float hl = srcL ? __ldcg(&srcL[r * 64 + n]) : 0.f;
                float ht = srcT ? __ldcg(&srcT[r * 64 + n]) : 0.f;
                float hd = srcD ? __ldcg(&srcD[r * 64 + n]) : 0.f;
                float pre = __ldcg(&g_xWij[t * 4096 + r * 64 + n]) + p[q];
                pre = fminf(fmaxf(pre, -15.f), 15.f);
                float e2 = __expf(2.f * pre);
                float hh = (e2 - 1.f) / (e2 + 1.f);
                float h = (el * hl + et * ht + ed * hd + ei * hh) * inv;
                g_S[t * 4096 + r * 64 + n] = h;
                if (t == 1023) out[r * 64 + n] = h;
            }
            __threadfence();
            __syncthreads();
            if (tid == 0) atomicAdd(&g_hdone[t], 1);
        }
    }
}

// ---------------------------------------------------------------------------
extern "C" void kernel_launch(void* const* d_in, const int* in_sizes, int n_in,
                              void* d_out, int out_size) {
    const float* in   = (const float*)d_in[0];  // (64,64,32,32)
    const float* W    = (const float*)d_in[1];  // (256,448)
    const float* Urec = (const float*)d_in[2];  // (192,64)
    const float* bias = (const float*)d_in[3];  // (512)
    const float* Wij  = (const float*)d_in[4];  // (64,64)
    float* out = (float*)d_out;                 // (64,64)

    static int smem_set = 0;
    if (!smem_set) {
        // 99072 B used; request 116736 to force 1 CTA/SM (no straggler SMs,
        // grid 148 <= SM count so all CTAs resident -> no spin deadlock).
        cudaFuncSetAttribute(k_scan, cudaFuncAttributeMaxDynamicSharedMemorySize,
                             116736);
        smem_set = 1;
    }

    k_init<<<4, 256>>>();
    k_transpose<<<dim3(32, 2, 64), dim3(32, 32)>>>(in);
    k_pre<<<dim3(1024, 8), TPB>>>(W, Wij, bias);
    k_scan<<<G, TPB, 116736>>>(W, Urec, out);
}

// round 12
// speedup vs baseline: 1.3248x; 1.3248x over previous
#include <cuda_runtime.h>
#include <cuda_bf16.h>
#include <cstdint>
#include <math.h>

// SpatialGRU 32x32, B=64,U=64,C=64.
// R10: warp-level mma.sync bf16 (hi/lo 3-term) for both GEMMs. 147 persistent
// CTAs = 21 groups x 7 N-slices; W/U slices smem-resident; Z in place in g_XZ.

#define TPB 256
#define NG  21
#define NS  7
#define GRID (NG * NS)

__device__ float g_x[1024 * 4096];      // x[t][b][c]
__device__ float g_XZ[1024 * 28672];    // x@W+bias (col-major [c448][r64]) -> Z
__device__ float g_xWij[1024 * 4096];   // x@W_ij + b_ij  [t][r][n]
__device__ float g_S[1024 * 4096];      // h state [t][r][n]
__device__ int g_zdone[1024];           // bitmask of 7 slices
__device__ int g_hdone[1024];           // bitmask of 7 slices (127 = full)

// smem byte offsets
#define AHI 0
#define ALO 25600
#define WHI 51200
#define WLO 76800
#define UHI 102400
#define ULO 108800
#define ZST 115200
#define SMEMSZ 131840
#define LDA 200                          // bf16 elems per smem row (400 B)

static __device__ __forceinline__ void mma16816(float* c, const uint32_t* a,
                                                const uint32_t* b) {
    asm volatile(
        "mma.sync.aligned.m16n8k16.row.col.f32.bf16.bf16.f32 "
        "{%0,%1,%2,%3}, {%4,%5,%6,%7}, {%8,%9}, {%0,%1,%2,%3};"
        : "+f"(c[0]), "+f"(c[1]), "+f"(c[2]), "+f"(c[3])
        : "r"(a[0]), "r"(a[1]), "r"(a[2]), "r"(a[3]), "r"(b[0]), "r"(b[1]));
}

// ---------------------------------------------------------------------------
__global__ void k_init() {
    int idx = blockIdx.x * blockDim.x + threadIdx.x;
    if (idx < 1024) { g_zdone[idx] = 0; g_hdone[idx] = 0; }
}

__global__ void k_transpose(const float* __restrict__ in) {
    __shared__ float tile[32][33];
    int b = blockIdx.z, t0 = blockIdx.x * 32, c0 = blockIdx.y * 32;
    int tx = threadIdx.x, ty = threadIdx.y;
    tile[ty][tx] = in[b * 65536 + (c0 + ty) * 1024 + t0 + tx];
    __syncthreads();
    g_x[(t0 + ty) * 4096 + b * 64 + c0 + tx] = tile[tx][ty];
}

// XZ[t] = x@W[192:256]+bias[:448] (col-major); xWij[t] = x@W_ij + bias[448:]
__global__ void k_pre(const float* __restrict__ W, const float* __restrict__ Wij,
                      const float* __restrict__ bias) {
    __shared__ float sXT[64 * 65];
    __shared__ float sB[64 * 64];
    int t = blockIdx.x, ct = blockIdx.y, tid = threadIdx.x;
    for (int idx = tid; idx < 4096; idx += TPB) {
        int rr = idx >> 6, k = idx & 63;
        sXT[k * 65 + rr] = g_x[t * 4096 + idx];
        sB[idx] = (ct < 7) ? W[(192 + rr) * 448 + ct * 64 + k] : Wij[rr * 64 + k];
    }
    __syncthreads();
    int r = tid & 63, cb = (tid >> 6) << 4;
    const float* bs = (ct < 7) ? (bias + ct * 64 + cb) : (bias + 448 + cb);
    float acc[16];
#pragma unroll
    for (int s = 0; s < 16; ++s) acc[s] = bs[s];
#pragma unroll 4
    for (int k = 0; k < 64; ++k) {
        float a = sXT[k * 65 + r];
        const float4* bp = (const float4*)&sB[k * 64 + cb];
        float4 b0 = bp[0], b1 = bp[1], b2 = bp[2], b3 = bp[3];
        acc[0] += a*b0.x; acc[1] += a*b0.y; acc[2] += a*b0.z; acc[3] += a*b0.w;
        acc[4] += a*b1.x; acc[5] += a*b1.y; acc[6] += a*b1.z; acc[7] += a*b1.w;
        acc[8] += a*b2.x; acc[9] += a*b2.y; acc[10] += a*b2.z; acc[11] += a*b2.w;
        acc[12] += a*b3.x; acc[13] += a*b3.y; acc[14] += a*b3.z; acc[15] += a*b3.w;
    }
    __syncthreads();
    if (ct < 7) {
#pragma unroll
        for (int s = 0; s < 16; ++s) sB[(cb + s) * 64 + r] = acc[s];
        __syncthreads();
        for (int idx = tid; idx < 4096; idx += TPB) {
            int c = idx >> 6, r2 = idx & 63;
            g_XZ[t * 28672 + (ct * 64 + c) * 64 + r2] = sB[c * 64 + r2];
        }
    } else {
        float* o = &g_xWij[t * 4096 + r * 64 + cb];
#pragma unroll
        for (int s = 0; s < 16; ++s) o[s] = acc[s];
    }
}

// ---------------------------------------------------------------------------
__global__ void __launch_bounds__(TPB, 1)
k_scan(const float* __restrict__ W, const float* __restrict__ Urec,
       float* __restrict__ out) {
    extern __shared__ char sm[];
    __nv_bfloat16* Ah = (__nv_bfloat16*)(sm + AHI);
    __nv_bfloat16* Al = (__nv_bfloat16*)(sm + ALO);
    __nv_bfloat16* Wh = (__nv_bfloat16*)(sm + WHI);
    __nv_bfloat16* Wl = (__nv_bfloat16*)(sm + WLO);
    __nv_bfloat16* Uh = (__nv_bfloat16*)(sm + UHI);
    __nv_bfloat16* Ul = (__nv_bfloat16*)(sm + ULO);
    float* Zs = (float*)(sm + ZST);

    int tid = threadIdx.x, w = tid >> 5, lane = tid & 31;
    int gp = blockIdx.x / NS, s = blockIdx.x % NS;
    int g = lane >> 2, q = lane & 3;
    int cbase = 8 * s;
    int ncols = (s == 6) ? 16 : 8;

    // resident W slice (cols 64s..64s+64), bf16 hi/lo, [n][k] stride LDA
    for (int idx = tid; idx < 12288; idx += TPB) {
        int n = idx & 63, k = idx >> 6;
        float v = W[k * 448 + s * 64 + n];
        __nv_bfloat16 hi = __float2bfloat16(v);
        Wh[n * LDA + k] = hi;
        Wl[n * LDA + k] = __float2bfloat16(v - __bfloat162float(hi));
    }
    // resident U slice, rows permuted to A k-order [top|left|diag]
    for (int idx = tid; idx < 16 * 192; idx += TPB) {
        int n = idx & 15, k = idx >> 4;
        if (n < ncols) {
            int ks = k < 64 ? k + 64 : (k < 128 ? k - 64 : k);
            float v = Urec[ks * 64 + cbase + n];
            __nv_bfloat16 hi = __float2bfloat16(v);
            Uh[n * LDA + k] = hi;
            Ul[n * LDA + k] = __float2bfloat16(v - __bfloat162float(hi));
        }
    }
    __syncthreads();

    for (int d = 0; d < 63; ++d) {
        int i0 = d > 31 ? d - 31 : 0;
        int nc = (d < 32) ? d + 1 : 63 - d;
        for (int c = gp; c < nc; c += NG) {
            int i = i0 + c, j = d - i, t = i * 32 + j;
            const float* spT = (i > 0) ? &g_S[(t - 32) * 4096] : (const float*)0;
            const float* spL = (j > 0) ? &g_S[(t - 1) * 4096] : (const float*)0;
            const float* spD = (i > 0 && j > 0) ? &g_S[(t - 33) * 4096] : (const float*)0;
            float* zb = &g_XZ[t * 28672];

            if (tid == 0) {
                volatile int* hd = g_hdone;
                if (spT) while (hd[t - 32] != 127) {}
                if (spL) while (hd[t - 1] != 127) {}
                if (spD) while (hd[t - 33] != 127) {}
            }
            __syncthreads();

            // A = hcat (q order: top|left|diag), bf16 hi/lo
            for (int idx = tid; idx < 12288; idx += TPB) {
                int rr = idx / 192, rem = idx - rr * 192;
                int blk = rem >> 6, cc = rem & 63;
                const float* hp = blk == 0 ? spT : (blk == 1 ? spL : spD);
                float v = hp ? __ldcg(&hp[rr * 64 + cc]) : 0.f;
                __nv_bfloat16 hi = __float2bfloat16(v);
                Ah[rr * LDA + rem] = hi;
                Al[rr * LDA + rem] = __float2bfloat16(v - __bfloat162float(hi));
            }
            __syncthreads();

            // ---- phase1 GEMM: Z slice (64x64), K=192, 3-term bf16 ----
            {
                int rb = (w & 3) * 16, nb0 = (w >> 2) * 32;
                float C[4][4];
#pragma unroll
                for (int a = 0; a < 4; ++a)
#pragma unroll
                    for (int b = 0; b < 4; ++b) C[a][b] = 0.f;
#pragma unroll 1
                for (int kc = 0; kc < 12; ++kc) {
                    int kb = kc * 16;
                    uint32_t ah[4], al[4];
                    ah[0] = *(const uint32_t*)&Ah[(rb + g) * LDA + kb + q * 2];
                    ah[1] = *(const uint32_t*)&Ah[(rb + g + 8) * LDA + kb + q * 2];
                    ah[2] = *(const uint32_t*)&Ah[(rb + g) * LDA + kb + 8 + q * 2];
                    ah[3] = *(const uint32_t*)&Ah[(rb + g + 8) * LDA + kb + 8 + q * 2];
                    al[0] = *(const uint32_t*)&Al[(rb + g) * LDA + kb + q * 2];
                    al[1] = *(const uint32_t*)&Al[(rb + g + 8) * LDA + kb + q * 2];
                    al[2] = *(const uint32_t*)&Al[(rb + g) * LDA + kb + 8 + q * 2];
                    al[3] = *(const uint32_t*)&Al[(rb + g + 8) * LDA + kb + 8 + q * 2];
#pragma unroll
                    for (int nblk = 0; nblk < 4; ++nblk) {
                        int n = nb0 + nblk * 8 + g;
                        uint32_t bh[2], bl[2];
                        bh[0] = *(const uint32_t*)&Wh[n * LDA + kb + q * 2];
                        bh[1] = *(const uint32_t*)&Wh[n * LDA + kb + 8 + q * 2];
                        bl[0] = *(const uint32_t*)&Wl[n * LDA + kb + q * 2];
                        bl[1] = *(const uint32_t*)&Wl[n * LDA + kb + 8 + q * 2];
                        mma16816(C[nblk], ah, bh);
                        mma16816(C[nblk], al, bh);
                        mma16816(C[nblk], ah, bl);
                    }
                }
                // stage to smem for coalesced global write
#pragma unroll
                for (int nblk = 0; nblk < 4; ++nblk) {
                    int c0 = nb0 + nblk * 8 + q * 2;
                    Zs[c0 * 65 + rb + g] = C[nblk][0];
                    Zs[(c0 + 1) * 65 + rb + g] = C[nblk][1];
                    Zs[c0 * 65 + rb + g + 8] = C[nblk][2];
                    Zs[(c0 + 1) * 65 + rb + g + 8] = C[nblk][3];
                }
            }
            __syncthreads();
            for (int idx = tid; idx < 4096; idx += TPB) {
                int cc = idx >> 6, r2 = idx & 63;
                float* p = &zb[(s * 64 + cc) * 64 + r2];
                *p = Zs[cc * 65 + r2] + __ldcg(p);
            }
            __threadfence();
            __syncthreads();
            if (tid == 0) atomicOr(&g_zdone[t], 1 << s);

            // ---- phase2 ----
            if (tid == 0) { volatile int* zd = g_zdone; while ((zd[t] & 7) != 7) {} }
            __syncthreads();

            // G = sigmoid(z)*hcat, in place over A (k stays in A-order)
            for (int idx = tid; idx < 12288; idx += TPB) {
                int c2 = idx >> 6, rr = idx & 63;
                int zc = c2 < 64 ? c2 + 64 : (c2 < 128 ? c2 - 64 : c2);
                float z = __ldcg(&zb[zc * 64 + rr]);
                float sg = 1.f / (1.f + __expf(-z));
                float v = sg * (__bfloat162float(Ah[rr * LDA + c2]) +
                                __bfloat162float(Al[rr * LDA + c2]));
                __nv_bfloat16 hi = __float2bfloat16(v);
                Ah[rr * LDA + c2] = hi;
                Al[rr * LDA + c2] = __float2bfloat16(v - __bfloat162float(hi));
            }
            __syncthreads();

            // P = G @ U slice
            float P[4] = {0.f, 0.f, 0.f, 0.f};
            int rb = (w & 3) * 16, nblk = w >> 2;
            bool active = (nblk == 0) || (s == 6);
            if (active) {
#pragma unroll 1
                for (int kc = 0; kc < 12; ++kc) {
                    int kb = kc * 16;
                    uint32_t ah[4], al[4], bh[2], bl[2];
                    ah[0] = *(const uint32_t*)&Ah[(rb + g) * LDA + kb + q * 2];
                    ah[1] = *(const uint32_t*)&Ah[(rb + g + 8) * LDA + kb + q * 2];
                    ah[2] = *(const uint32_t*)&Ah[(rb + g) * LDA + kb + 8 + q * 2];
                    ah[3] = *(const uint32_t*)&Ah[(rb + g + 8) * LDA + kb + 8 + q * 2];
                    al[0] = *(const uint32_t*)&Al[(rb + g) * LDA + kb + q * 2];
                    al[1] = *(const uint32_t*)&Al[(rb + g + 8) * LDA + kb + q * 2];
                    al[2] = *(const uint32_t*)&Al[(rb + g) * LDA + kb + 8 + q * 2];
                    al[3] = *(const uint32_t*)&Al[(rb + g + 8) * LDA + kb + 8 + q * 2];
                    int n = nblk * 8 + g;
                    bh[0] = *(const uint32_t*)&Uh[n * LDA + kb + q * 2];
                    bh[1] = *(const uint32_t*)&Uh[n * LDA + kb + 8 + q * 2];
                    bl[0] = *(const uint32_t*)&Ul[n * LDA + kb + q * 2];
                    bl[1] = *(const uint32_t*)&Ul[n * LDA + kb + 8 + q * 2];
                    mma16816(P, ah, bh);
                    mma16816(P, al, bh);
                    mma16816(P, ah, bl);
                }
            }

            if (tid == 0) { volatile int* zd = g_zdone; while (zd[t] != 127) {} }
            __syncthreads();

            if (active) {
                const float* xw = &g_xWij[t * 4096];
#pragma unroll
                for (int fr = 0; fr < 4; ++fr) {
                    int row = rb + g + ((fr & 2) ? 8 : 0);
                    int n = cbase + nblk * 8 + q * 2 + (fr & 1);
                    float zi = __ldcg(&zb[(192 + n) * 64 + row]);
                    float zl = __ldcg(&zb[(256 + n) * 64 + row]);
                    float zt = __ldcg(&zb[(320 + n) * 64 + row]);
                    float zd_ = __ldcg(&zb[(384 + n) * 64 + row]);
                    float m = fmaxf(fmaxf(zi, zl), fmaxf(zt, zd_));
                    float ei = __expf(zi - m), el = __expf(zl - m);
                    float et = __expf(zt - m), ed = __expf(zd_ - m);
                    float inv = 1.f / (ei + el + et + ed);
                    float hl = spL ? __ldcg(&spL[row * 64 + n]) : 0.f;
                    float ht = spT ? __ldcg(&spT[row * 64 + n]) : 0.f;
                    float hd2 = spD ? __ldcg(&spD[row * 64 + n]) : 0.f;
                    float pre = __ldcg(&xw[row * 64 + n]) + P[fr];
                    pre = fminf(fmaxf(pre, -15.f), 15.f);
                    float e2 = __expf(2.f * pre);
                    float hh = (e2 - 1.f) / (e2 + 1.f);
                    float h = (el * hl + et * ht + ed * hd2 + ei * hh) * inv;
                    g_S[t * 4096 + row * 64 + n] = h;
                    if (t == 1023) out[row * 64 + n] = h;
                }
            }
            __threadfence();
            __syncthreads();
            if (tid == 0) atomicOr(&g_hdone[t], 1 << s);
        }
    }
}

// ---------------------------------------------------------------------------
extern "C" void kernel_launch(void* const* d_in, const int* in_sizes, int n_in,
                              void* d_out, int out_size) {
    const float* in   = (const float*)d_in[0];  // (64,64,32,32)
    const float* W    = (const float*)d_in[1];  // (256,448)
    const float* Urec = (const float*)d_in[2];  // (192,64)
    const float* bias = (const float*)d_in[3];  // (512)
    const float* Wij  = (const float*)d_in[4];  // (64,64)
    float* out = (float*)d_out;                 // (64,64)

    static int done = 0;
    if (!done) {
        cudaFuncSetAttribute(k_scan, cudaFuncAttributeMaxDynamicSharedMemorySize,
                             SMEMSZ);
        done = 1;
    }
    k_init<<<4, 256>>>();
    k_transpose<<<dim3(32, 2, 64), dim3(32, 32)>>>(in);
    k_pre<<<dim3(1024, 8), TPB>>>(W, Wij, bias);
    k_scan<<<GRID, TPB, SMEMSZ>>>(W, Urec, out);
}

// round 13
// speedup vs baseline: 2.6726x; 2.0174x over previous
#include <cuda_runtime.h>
#include <cuda_bf16.h>
#include <cstdint>
#include <math.h>

// SpatialGRU 32x32, B=64,U=64,C=64.
// R13: 21 groups x 7 slices persistent. r-slices (0-2): Z_r stays in smem ->
// G -> split-K partial P_s to L2. z-slices (3-6): Z_z to L2 + 16-col epilogue
// (h from smem A). Packed bf16 hi/lo h in global; release/acquire flags.

#define TPB 256
#define NG  21
#define NS  7
#define GRID (NG*NS)
#define LDA 200
#define LDU 72
#define LDZ 65

__device__ float    g_x[1024 * 4096];
__device__ float    g_XZ[1024 * 28672];   // col-major [c448][r64]; z-cols -> Z
__device__ float    g_xWij[1024 * 4096];
__device__ uint32_t g_Spk[1024 * 4096];   // packed h: lo16 = hi-bf16, hi16 = lo-bf16
__device__ float    g_P[1024 * 3 * 4096]; // per-cell partials, col-major [n][r]
__device__ int      g_pz[1024];           // bits 0-2: P_s ready, 3-6: Z_s ready
__device__ int      g_hdone[1024];        // bits 0-3 (slices 3-6); full = 15

static __device__ __forceinline__ void mma16816(float* c, const uint32_t* a,
                                                const uint32_t* b) {
    asm volatile(
        "mma.sync.aligned.m16n8k16.row.col.f32.bf16.bf16.f32 "
        "{%0,%1,%2,%3}, {%4,%5,%6,%7}, {%8,%9}, {%0,%1,%2,%3};"
        : "+f"(c[0]), "+f"(c[1]), "+f"(c[2]), "+f"(c[3])
        : "r"(a[0]), "r"(a[1]), "r"(a[2]), "r"(a[3]), "r"(b[0]), "r"(b[1]));
}
static __device__ __forceinline__ int ld_acq(const int* p) {
    int v;
    asm volatile("ld.acquire.gpu.global.b32 %0, [%1];" : "=r"(v) : "l"(p) : "memory");
    return v;
}
static __device__ __forceinline__ void red_rel_or(int* p, int v) {
    asm volatile("red.release.gpu.global.or.b32 [%0], %1;" :: "l"(p), "r"(v) : "memory");
}

// ---------------------------------------------------------------------------
__global__ void k_init() {
    int idx = blockIdx.x * blockDim.x + threadIdx.x;
    if (idx < 1024) { g_pz[idx] = 0; g_hdone[idx] = 0; }
}

__global__ void k_transpose(const float* __restrict__ in) {
    __shared__ float tile[32][33];
    int b = blockIdx.z, t0 = blockIdx.x * 32, c0 = blockIdx.y * 32;
    int tx = threadIdx.x, ty = threadIdx.y;
    tile[ty][tx] = in[b * 65536 + (c0 + ty) * 1024 + t0 + tx];
    __syncthreads();
    g_x[(t0 + ty) * 4096 + b * 64 + c0 + tx] = tile[tx][ty];
}

// XZ[t] = x@W[192:256]+bias[:448] (col-major [c][r]); xWij[t] = x@W_ij + b_ij
__global__ void k_pre(const float* __restrict__ W, const float* __restrict__ Wij,
                      const float* __restrict__ bias) {
    __shared__ float sXT[64 * 65];
    __shared__ float sB[64 * 64];
    int t = blockIdx.x, ct = blockIdx.y, tid = threadIdx.x;
    for (int idx = tid; idx < 4096; idx += TPB) {
        int rr = idx >> 6, k = idx & 63;
        sXT[k * 65 + rr] = g_x[t * 4096 + idx];
        sB[idx] = (ct < 7) ? W[(192 + rr) * 448 + ct * 64 + k] : Wij[rr * 64 + k];
    }
    __syncthreads();
    int r = tid & 63, cb = (tid >> 6) << 4;
    const float* bs = (ct < 7) ? (bias + ct * 64 + cb) : (bias + 448 + cb);
    float acc[16];
#pragma unroll
    for (int s = 0; s < 16; ++s) acc[s] = bs[s];
#pragma unroll 4
    for (int k = 0; k < 64; ++k) {
        float a = sXT[k * 65 + r];
        const float4* bp = (const float4*)&sB[k * 64 + cb];
        float4 b0 = bp[0], b1 = bp[1], b2 = bp[2], b3 = bp[3];
        acc[0] += a*b0.x; acc[1] += a*b0.y; acc[2] += a*b0.z; acc[3] += a*b0.w;
        acc[4] += a*b1.x; acc[5] += a*b1.y; acc[6] += a*b1.z; acc[7] += a*b1.w;
        acc[8] += a*b2.x; acc[9] += a*b2.y; acc[10] += a*b2.z; acc[11] += a*b2.w;
        acc[12] += a*b3.x; acc[13] += a*b3.y; acc[14] += a*b3.z; acc[15] += a*b3.w;
    }
    __syncthreads();
    if (ct < 7) {
#pragma unroll
        for (int s = 0; s < 16; ++s) sB[(cb + s) * 64 + r] = acc[s];
        __syncthreads();
        for (int idx = tid; idx < 4096; idx += TPB) {
            int c = idx >> 6, r2 = idx & 63;
            g_XZ[t * 28672 + (ct * 64 + c) * 64 + r2] = sB[c * 64 + r2];
        }
    } else {
        float* o = &g_xWij[t * 4096 + r * 64 + cb];
#pragma unroll
        for (int s = 0; s < 16; ++s) o[s] = acc[s];
    }
}

// ---------------------------------------------------------------------------
__global__ void __launch_bounds__(TPB, 1)
k_scan(const float* __restrict__ W, const float* __restrict__ Urec,
       float* __restrict__ out) {
    extern __shared__ char sm[];
    __nv_bfloat16* Ah = (__nv_bfloat16*)(sm);
    __nv_bfloat16* Al = (__nv_bfloat16*)(sm + 25600);
    __nv_bfloat16* Wh = (__nv_bfloat16*)(sm + 51200);
    __nv_bfloat16* Wl = (__nv_bfloat16*)(sm + 76800);
    __nv_bfloat16* Uh = (__nv_bfloat16*)(sm + 102400);
    __nv_bfloat16* Ul = (__nv_bfloat16*)(sm + 111616);
    __nv_bfloat16* Gh = (__nv_bfloat16*)(sm + 120832);
    __nv_bfloat16* Gl = (__nv_bfloat16*)(sm + 130048);
    float*         Zs = (float*)(sm + 139264);

    int tid = threadIdx.x, w = tid >> 5, lane = tid & 31;
    int g = lane >> 2, q = lane & 3;
    int gp = blockIdx.x / NS, s = blockIdx.x % NS;

    // resident W slice (cols 64s..64s+64), [n][k]
    for (int idx = tid; idx < 12288; idx += TPB) {
        int n = idx & 63, k = idx >> 6;
        float v = W[k * 448 + s * 64 + n];
        __nv_bfloat16 hi = __float2bfloat16(v);
        Wh[n * LDA + k] = hi;
        Wl[n * LDA + k] = __float2bfloat16(v - __bfloat162float(hi));
    }
    // resident U_s (rows 64s..64s+64 of Urec), [n][k]
    if (s < 3)
        for (int idx = tid; idx < 4096; idx += TPB) {
            int n = idx & 63, k = idx >> 6;
            float v = Urec[(s * 64 + k) * 64 + n];
            __nv_bfloat16 hi = __float2bfloat16(v);
            Uh[n * LDU + k] = hi;
            Ul[n * LDU + k] = __float2bfloat16(v - __bfloat162float(hi));
        }
    __syncthreads();

    for (int d = 0; d < 63; ++d) {
        int i0 = d > 31 ? d - 31 : 0;
        int nc = (d < 32) ? d + 1 : 63 - d;
        for (int c = gp; c < nc; c += NG) {
            int i = i0 + c, j = d - i, t = i * 32 + j;
            const uint32_t* hpT = (i > 0) ? &g_Spk[(t - 32) * 4096] : (const uint32_t*)0;
            const uint32_t* hpL = (j > 0) ? &g_Spk[(t - 1) * 4096] : (const uint32_t*)0;
            const uint32_t* hpD = (i > 0 && j > 0) ? &g_Spk[(t - 33) * 4096] : (const uint32_t*)0;
            float* zb = &g_XZ[t * 28672];

            if (tid == 0 && hpT)  while (ld_acq(&g_hdone[t - 32]) != 15) {}
            if (tid == 32 && hpL) while (ld_acq(&g_hdone[t - 1])  != 15) {}
            if (tid == 64 && hpD) while (ld_acq(&g_hdone[t - 33]) != 15) {}
            __syncthreads();

            // ---- A build: [top|left|diag], packed uint4 loads ----
            const uint4* bp3[3] = {(const uint4*)hpT, (const uint4*)hpL, (const uint4*)hpD};
#pragma unroll
            for (int it = 0; it < 12; ++it) {
                int idx = tid + it * TPB;
                int blk = idx >> 10, row = (idx >> 4) & 63, c4 = idx & 15;
                const uint4* p = bp3[blk];
                uint4 v = p ? __ldcg(&p[row * 16 + c4]) : make_uint4(0, 0, 0, 0);
                int cc = blk * 64 + c4 * 4;
                uint32_t* ah = (uint32_t*)&Ah[row * LDA + cc];
                uint32_t* al = (uint32_t*)&Al[row * LDA + cc];
                ah[0] = (v.x & 0xFFFFu) | (v.y << 16);
                ah[1] = (v.z & 0xFFFFu) | (v.w << 16);
                al[0] = (v.x >> 16) | (v.y & 0xFFFF0000u);
                al[1] = (v.z >> 16) | (v.w & 0xFFFF0000u);
            }
            __syncthreads();

            // ---- Z MMA: 64x64, K=192, 3-term ----
            {
                int rb = (w & 3) * 16, nb0 = (w >> 2) * 32;
                float C[4][4];
#pragma unroll
                for (int a = 0; a < 4; ++a)
#pragma unroll
                    for (int b = 0; b < 4; ++b) C[a][b] = 0.f;
#pragma unroll 1
                for (int kc = 0; kc < 12; ++kc) {
                    int kb = kc * 16;
                    uint32_t ah[4], al[4];
                    ah[0] = *(const uint32_t*)&Ah[(rb + g) * LDA + kb + q * 2];
                    ah[1] = *(const uint32_t*)&Ah[(rb + g + 8) * LDA + kb + q * 2];
                    ah[2] = *(const uint32_t*)&Ah[(rb + g) * LDA + kb + 8 + q * 2];
                    ah[3] = *(const uint32_t*)&Ah[(rb + g + 8) * LDA + kb + 8 + q * 2];
                    al[0] = *(const uint32_t*)&Al[(rb + g) * LDA + kb + q * 2];
                    al[1] = *(const uint32_t*)&Al[(rb + g + 8) * LDA + kb + q * 2];
                    al[2] = *(const uint32_t*)&Al[(rb + g) * LDA + kb + 8 + q * 2];
                    al[3] = *(const uint32_t*)&Al[(rb + g + 8) * LDA + kb + 8 + q * 2];
#pragma unroll
                    for (int nblk = 0; nblk < 4; ++nblk) {
                        int n = nb0 + nblk * 8 + g;
                        uint32_t bh[2], bl[2];
                        bh[0] = *(const uint32_t*)&Wh[n * LDA + kb + q * 2];
                        bh[1] = *(const uint32_t*)&Wh[n * LDA + kb + 8 + q * 2];
                        bl[0] = *(const uint32_t*)&Wl[n * LDA + kb + q * 2];
                        bl[1] = *(const uint32_t*)&Wl[n * LDA + kb + 8 + q * 2];
                        mma16816(C[nblk], ah, bh);
                        mma16816(C[nblk], al, bh);
                        mma16816(C[nblk], ah, bl);
                    }
                }
#pragma unroll
                for (int nblk = 0; nblk < 4; ++nblk) {
                    int c0 = nb0 + nblk * 8 + q * 2;
                    Zs[c0 * LDZ + rb + g] = C[nblk][0];
                    Zs[(c0 + 1) * LDZ + rb + g] = C[nblk][1];
                    Zs[c0 * LDZ + rb + g + 8] = C[nblk][2];
                    Zs[(c0 + 1) * LDZ + rb + g + 8] = C[nblk][3];
                }
            }
            __syncthreads();

            if (s >= 3) {
                // ---- z-slice: add XZ, publish Z ----
#pragma unroll
                for (int it = 0; it < 16; ++it) {
                    int idx = tid + it * TPB;
                    int cc = idx >> 6, r2 = idx & 63;
                    float* p = &zb[(s * 64 + cc) * 64 + r2];
                    __stcg(p, Zs[cc * LDZ + r2] + __ldcg(p));
                }
                __syncthreads();
                if (tid == 0) {
                    red_rel_or(&g_pz[t], 1 << s);
                    while (ld_acq(&g_pz[t]) != 0x7F) {}
                }
                __syncthreads();

                // ---- epilogue: 16 cols ----
                int n = 16 * (s - 3) + (tid & 15);
                int r0 = (tid >> 4) * 4;
                float4 p0 = __ldcg((const float4*)&g_P[(t * 3 + 0) * 4096 + n * 64 + r0]);
                float4 p1 = __ldcg((const float4*)&g_P[(t * 3 + 1) * 4096 + n * 64 + r0]);
                float4 p2 = __ldcg((const float4*)&g_P[(t * 3 + 2) * 4096 + n * 64 + r0]);
                float4 zi4 = __ldcg((const float4*)&zb[(192 + n) * 64 + r0]);
                float4 zl4 = __ldcg((const float4*)&zb[(256 + n) * 64 + r0]);
                float4 zt4 = __ldcg((const float4*)&zb[(320 + n) * 64 + r0]);
                float4 zd4 = __ldcg((const float4*)&zb[(384 + n) * 64 + r0]);
#pragma unroll
                for (int e = 0; e < 4; ++e) {
                    int row = r0 + e;
                    float zi = (&zi4.x)[e], zl = (&zl4.x)[e];
                    float zt = (&zt4.x)[e], zd = (&zd4.x)[e];
                    float m = fmaxf(fmaxf(zi, zl), fmaxf(zt, zd));
                    float ei = __expf(zi - m), el = __expf(zl - m);
                    float et = __expf(zt - m), ed = __expf(zd - m);
                    float inv = 1.f / (ei + el + et + ed);
                    float ht = __bfloat162float(Ah[row * LDA + n]) +
                               __bfloat162float(Al[row * LDA + n]);
                    float hl = __bfloat162float(Ah[row * LDA + 64 + n]) +
                               __bfloat162float(Al[row * LDA + 64 + n]);
                    float hd = __bfloat162float(Ah[row * LDA + 128 + n]) +
                               __bfloat162float(Al[row * LDA + 128 + n]);
                    float pre = __ldcg(&g_xWij[t * 4096 + row * 64 + n]) +
                                (&p0.x)[e] + (&p1.x)[e] + (&p2.x)[e];
                    pre = fminf(fmaxf(pre, -15.f), 15.f);
                    float e2 = __expf(2.f * pre);
                    float hh = (e2 - 1.f) / (e2 + 1.f);
                    float h = (el * hl + et * ht + ed * hd + ei * hh) * inv;
                    __nv_bfloat16 hhi = __float2bfloat16(h);
                    __nv_bfloat16 hlo = __float2bfloat16(h - __bfloat162float(hhi));
                    uint32_t pk = (uint32_t)__bfloat16_as_ushort(hhi) |
                                  ((uint32_t)__bfloat16_as_ushort(hlo) << 16);
                    __stcg(&g_Spk[t * 4096 + row * 64 + n], pk);
                    if (t == 1023) out[row * 64 + n] = h;
                }
                __syncthreads();
                if (tid == 0) red_rel_or(&g_hdone[t], 1 << (s - 3));
            } else {
                // ---- r-slice: G = sigmoid(Z_r + XZ) * h_blk ----
                int amap = (s == 0) ? 64 : (s == 1 ? 0 : 128);
#pragma unroll
                for (int it = 0; it < 16; ++it) {
                    int idx = tid + it * TPB;
                    int cc = idx >> 6, r2 = idx & 63;
                    float z = Zs[cc * LDZ + r2] + __ldcg(&zb[(s * 64 + cc) * 64 + r2]);
                    float sg = 1.f / (1.f + __expf(-z));
                    int ca = amap + cc;
                    float a = __bfloat162float(Ah[r2 * LDA + ca]) +
                              __bfloat162float(Al[r2 * LDA + ca]);
                    float v = sg * a;
                    __nv_bfloat16 hi = __float2bfloat16(v);
                    Gh[r2 * LDU + cc] = hi;
                    Gl[r2 * LDU + cc] = __float2bfloat16(v - __bfloat162float(hi));
                }
                __syncthreads();

                // ---- P_s = G_s @ U_s (64x64, K=64, 3-term) ----
                {
                    int rb = (w & 3) * 16, nb0 = (w >> 2) * 32;
                    float C[4][4];
#pragma unroll
                    for (int a = 0; a < 4; ++a)
#pragma unroll
                        for (int b = 0; b < 4; ++b) C[a][b] = 0.f;
#pragma unroll
                    for (int kc = 0; kc < 4; ++kc) {
                        int kb = kc * 16;
                        uint32_t ah[4], al[4];
                        ah[0] = *(const uint32_t*)&Gh[(rb + g) * LDU + kb + q * 2];
                        ah[1] = *(const uint32_t*)&Gh[(rb + g + 8) * LDU + kb + q * 2];
                        ah[2] = *(const uint32_t*)&Gh[(rb + g) * LDU + kb + 8 + q * 2];
                        ah[3] = *(const uint32_t*)&Gh[(rb + g + 8) * LDU + kb + 8 + q * 2];
                        al[0] = *(const uint32_t*)&Gl[(rb + g) * LDU + kb + q * 2];
                        al[1] = *(const uint32_t*)&Gl[(rb + g + 8) * LDU + kb + q * 2];
                        al[2] = *(const uint32_t*)&Gl[(rb + g) * LDU + kb + 8 + q * 2];
                        al[3] = *(const uint32_t*)&Gl[(rb + g + 8) * LDU + kb + 8 + q * 2];
#pragma unroll
                        for (int nblk = 0; nblk < 4; ++nblk) {
                            int n = nb0 + nblk * 8 + g;
                            uint32_t bh[2], bl[2];
                            bh[0] = *(const uint32_t*)&Uh[n * LDU + kb + q * 2];
                            bh[1] = *(const uint32_t*)&Uh[n * LDU + kb + 8 + q * 2];
                            bl[0] = *(const uint32_t*)&Ul[n * LDU + kb + q * 2];
                            bl[1] = *(const uint32_t*)&Ul[n * LDU + kb + 8 + q * 2];
                            mma16816(C[nblk], ah, bh);
                            mma16816(C[nblk], al, bh);
                            mma16816(C[nblk], ah, bl);
                        }
                    }
#pragma unroll
                    for (int nblk = 0; nblk < 4; ++nblk) {
                        int c0 = nb0 + nblk * 8 + q * 2;
                        Zs[c0 * LDZ + rb + g] = C[nblk][0];
                        Zs[(c0 + 1) * LDZ + rb + g] = C[nblk][1];
                        Zs[c0 * LDZ + rb + g + 8] = C[nblk][2];
                        Zs[(c0 + 1) * LDZ + rb + g + 8] = C[nblk][3];
                    }
                }
                __syncthreads();
#pragma unroll
                for (int it = 0; it < 16; ++it) {
                    int idx = tid + it * TPB;
                    int n2 = idx >> 6, r2 = idx & 63;
                    __stcg(&g_P[(t * 3 + s) * 4096 + n2 * 64 + r2], Zs[n2 * LDZ + r2]);
                }
                __syncthreads();
                if (tid == 0) red_rel_or(&g_pz[t], 1 << s);
            }
        }
    }
}

// ---------------------------------------------------------------------------
extern "C" void kernel_launch(void* const* d_in, const int* in_sizes, int n_in,
                              void* d_out, int out_size) {
    const float* in   = (const float*)d_in[0];  // (64,64,32,32)
    const float* W    = (const float*)d_in[1];  // (256,448)
    const float* Urec = (const float*)d_in[2];  // (192,64)
    const float* bias = (const float*)d_in[3];  // (512)
    const float* Wij  = (const float*)d_in[4];  // (64,64)
    float* out = (float*)d_out;                 // (64,64)

    static int done = 0;
    if (!done) {
        cudaFuncSetAttribute(k_scan, cudaFuncAttributeMaxDynamicSharedMemorySize,
                             155904);
        done = 1;
    }
    k_init<<<4, 256>>>();
    k_transpose<<<dim3(32, 2, 64), dim3(32, 32)>>>(in);
    k_pre<<<dim3(1024, 8), TPB>>>(W, Wij, bias);
    k_scan<<<GRID, TPB, 155904>>>(W, Urec, out);
}